// round 7
// baseline (speedup 1.0000x reference)
#include <cuda_runtime.h>
#include <math.h>

#define Bdim 1024
#define Ndim 1024
#define Mdim 64
#define EPSV 1e-16f
#define COS_EPS 1e-8f

// ---------------------------------------------------------------------------
// cp.async helper
// ---------------------------------------------------------------------------
__device__ __forceinline__ void cp_async8(void* smem_dst, const void* gsrc) {
    unsigned s = (unsigned)__cvta_generic_to_shared(smem_dst);
    asm volatile("cp.async.ca.shared.global [%0], [%1], 8;" :: "r"(s), "l"(gsrc));
}
#define CP_COMMIT() asm volatile("cp.async.commit_group;")
#define CP_WAIT(N)  asm volatile("cp.async.wait_group %0;" :: "n"(N))

// ---------------------------------------------------------------------------
// Block-wide SUM reduction for 512 threads, 2 barriers.
// ---------------------------------------------------------------------------
__device__ __forceinline__ float blk_sum512(float v, float* red, int tid) {
    const int lane = tid & 31, warp = tid >> 5;   // 16 warps
#pragma unroll
    for (int o = 16; o > 0; o >>= 1)
        v += __shfl_xor_sync(0xffffffffu, v, o);
    if (lane == 0) red[warp] = v;
    __syncthreads();
    if (warp == 0) {
        float t = (lane < 16) ? red[lane] : 0.f;
#pragma unroll
        for (int o = 8; o > 0; o >>= 1)
            t += __shfl_xor_sync(0xffffffffu, t, o);
        if (lane == 0) red[16] = t;
    }
    __syncthreads();
    return red[16];
}

// ---------------------------------------------------------------------------
// Fused NTM step: one block per batch b, 512 threads, 3 blocks/SM.
// ---------------------------------------------------------------------------
__global__ void __launch_bounds__(512, 3) fused_ntm(
        const float* __restrict__ mem,   const float* __restrict__ kk,
        const float* __restrict__ beta,  const float* __restrict__ gg,
        const float* __restrict__ ss,    const float* __restrict__ gamma,
        const float* __restrict__ wprev, const float* __restrict__ ee,
        const float* __restrict__ aa,    float* __restrict__ out) {
    const int b   = blockIdx.x;
    const int tid = threadIdx.x;
    const int ml  = tid & 15;           // float4 lane within a row
    const int rg  = tid >> 4;           // row group 0..31

    __shared__ float  s_sc[Ndim];       // scores
    __shared__ float  s_wg[Ndim];       // interpolated weights
    __shared__ float  s_w [Ndim];       // final weights
    __shared__ float  s_wp[Ndim];       // prefetched wprev
    __shared__ float  redA[17];
    __shared__ float  redB[17];
    __shared__ float4 s_r[512];

    const float* mb = mem + (size_t)b * Ndim * Mdim;

    // prefetch wprev row into smem
    cp_async8(&s_wp[tid * 2], wprev + b * Ndim + tid * 2);
    CP_COMMIT();

    // ---- k (+eps) and its norm (reduced within each 16-lane group) ----
    float4 k4 = *(const float4*)(kk + b * Mdim + ml * 4);
    const float kx = k4.x + EPSV, ky = k4.y + EPSV;
    const float kz = k4.z + EPSV, kw = k4.w + EPSV;
    float kn = kx * kx + ky * ky + kz * kz + kw * kw;
#pragma unroll
    for (int o = 8; o > 0; o >>= 1) kn += __shfl_xor_sync(0xffffffffu, kn, o);
    const float knorm = fmaxf(sqrtf(kn), COS_EPS);
    const float bet = beta[b];

    // ---- Phase 1: scores. 8 groups x 4 front-batched LDG.128 ----
#pragma unroll
    for (int grp = 0; grp < 8; grp++) {
        float4 m[4];
#pragma unroll
        for (int j = 0; j < 4; j++) {
            const int n = grp * 128 + j * 32 + rg;
            m[j] = *(const float4*)(mb + (size_t)n * Mdim + ml * 4);
        }
#pragma unroll
        for (int j = 0; j < 4; j++) {
            const int n = grp * 128 + j * 32 + rg;
            const float ax = m[j].x + EPSV, ay = m[j].y + EPSV;
            const float az = m[j].z + EPSV, aw = m[j].w + EPSV;
            float d = ax * kx; d = fmaf(ay, ky, d); d = fmaf(az, kz, d); d = fmaf(aw, kw, d);
            float s = ax * ax; s = fmaf(ay, ay, s); s = fmaf(az, az, s); s = fmaf(aw, aw, s);
#pragma unroll
            for (int o = 8; o > 0; o >>= 1) {
                d += __shfl_xor_sync(0xffffffffu, d, o);
                s += __shfl_xor_sync(0xffffffffu, s, o);
            }
            if (ml == 0)
                s_sc[n] = bet * (d / (fmaxf(sqrtf(s), COS_EPS) * knorm));
        }
    }
    __syncthreads();

    // ---- Phase 2: softmax (no max: |score| <= ~1) / interpolate / shift /
    //      sharpen. 2 n per thread. ----
    {
        const int n0 = tid, n1 = tid + 512;
        const float ex0 = __expf(s_sc[n0]);
        const float ex1 = __expf(s_sc[n1]);
        const float esum = blk_sum512(ex0 + ex1, redA, tid);
        const float inv_esum = 1.f / esum;

        CP_WAIT(0);                         // wprev prefetch complete
        const float gv = gg[b];
        const float wp0 = s_wp[n0];
        const float wp1 = s_wp[n1];
        const float wg0 = fmaf(gv, ex0 * inv_esum - wp0, wp0);
        const float wg1 = fmaf(gv, ex1 * inv_esum - wp1, wp1);
        s_wg[n0] = wg0;
        s_wg[n1] = wg1;
        __syncthreads();

        const float s0 = ss[b * 3 + 0], s1 = ss[b * 3 + 1], s2 = ss[b * 3 + 2];
        const float gm = gamma[b];
        const float wh0 = s0 * s_wg[(n0 + Ndim - 1) & (Ndim - 1)]
                        + s1 * wg0 + s2 * s_wg[(n0 + 1) & (Ndim - 1)];
        const float wh1 = s0 * s_wg[(n1 + Ndim - 1) & (Ndim - 1)]
                        + s1 * wg1 + s2 * s_wg[(n1 + 1) & (Ndim - 1)];
        const float w0 = __powf(wh0, gm);
        const float w1 = __powf(wh1, gm);
        const float wsum = blk_sum512(w0 + w1, redB, tid);
        const float inv = 1.f / (wsum + EPSV);
        s_w[n0] = w0 * inv;
        s_w[n1] = w1 * inv;
    }
    __syncthreads();

    // ---- Phase 3: read vector + erase/add write (reverse order, batched) ----
    const float4 e4 = *(const float4*)(ee + b * Mdim + ml * 4);
    const float4 a4 = *(const float4*)(aa + b * Mdim + ml * 4);
    float* ob = out + (size_t)b * (Ndim + 1) * Mdim;

    float rx = 0.f, ry = 0.f, rz = 0.f, rw = 0.f;
#pragma unroll
    for (int grp = 7; grp >= 0; grp--) {
        float4 m[4];
#pragma unroll
        for (int j = 0; j < 4; j++) {
            const int n = grp * 128 + j * 32 + rg;
            m[j] = __ldcs((const float4*)(mb + (size_t)n * Mdim + ml * 4));
        }
#pragma unroll
        for (int j = 0; j < 4; j++) {
            const int n = grp * 128 + j * 32 + rg;
            const float wv = s_w[n];
            float4 o4;
            o4.x = fmaf(m[j].x, fmaf(-wv, e4.x, 1.f), wv * a4.x);
            o4.y = fmaf(m[j].y, fmaf(-wv, e4.y, 1.f), wv * a4.y);
            o4.z = fmaf(m[j].z, fmaf(-wv, e4.z, 1.f), wv * a4.z);
            o4.w = fmaf(m[j].w, fmaf(-wv, e4.w, 1.f), wv * a4.w);
            __stcs((float4*)(ob + (size_t)(1 + n) * Mdim + ml * 4), o4);
            rx = fmaf(wv, m[j].x, rx);
            ry = fmaf(wv, m[j].y, ry);
            rz = fmaf(wv, m[j].z, rz);
            rw = fmaf(wv, m[j].w, rw);
        }
    }

    // reduce read accumulators (512 -> 16 lanes of ml)
    s_r[tid] = make_float4(rx, ry, rz, rw);
    __syncthreads();
#pragma unroll
    for (int s = 256; s >= 16; s >>= 1) {
        if (tid < s) {
            float4 x = s_r[tid], y = s_r[tid + s];
            x.x += y.x; x.y += y.y; x.z += y.z; x.w += y.w;
            s_r[tid] = x;
        }
        __syncthreads();
    }
    if (tid < 16) __stcs((float4*)(ob + tid * 4), s_r[tid]);   // read row
}

// ---------------------------------------------------------------------------
extern "C" void kernel_launch(void* const* d_in, const int* in_sizes, int n_in,
                              void* d_out, int out_size) {
    const float* mem   = (const float*)d_in[0];
    const float* kk    = (const float*)d_in[1];
    const float* beta  = (const float*)d_in[2];
    const float* gg    = (const float*)d_in[3];
    const float* ss    = (const float*)d_in[4];
    const float* gamma = (const float*)d_in[5];
    const float* wprev = (const float*)d_in[6];
    const float* ee    = (const float*)d_in[7];
    const float* aa    = (const float*)d_in[8];
    float* out = (float*)d_out;

    fused_ntm<<<Bdim, 512>>>(mem, kk, beta, gg, ss, gamma, wprev, ee, aa, out);
}

// round 8
// speedup vs baseline: 1.1187x; 1.1187x over previous
#include <cuda_runtime.h>
#include <math.h>

#define Bdim 1024
#define Ndim 1024
#define Mdim 64
#define EPSV 1e-16f
#define COS_EPS 1e-8f

// ---------------------------------------------------------------------------
// cp.async helpers
// ---------------------------------------------------------------------------
__device__ __forceinline__ void cp_async16(void* smem_dst, const void* gsrc) {
    unsigned s = (unsigned)__cvta_generic_to_shared(smem_dst);
    asm volatile("cp.async.cg.shared.global [%0], [%1], 16;" :: "r"(s), "l"(gsrc));
}
__device__ __forceinline__ void cp_async8(void* smem_dst, const void* gsrc) {
    unsigned s = (unsigned)__cvta_generic_to_shared(smem_dst);
    asm volatile("cp.async.ca.shared.global [%0], [%1], 8;" :: "r"(s), "l"(gsrc));
}
#define CP_COMMIT() asm volatile("cp.async.commit_group;")
#define CP_WAIT(N)  asm volatile("cp.async.wait_group %0;" :: "n"(N))

// ---------------------------------------------------------------------------
// Block-wide SUM reduction for 512 threads, 2 barriers.
// ---------------------------------------------------------------------------
__device__ __forceinline__ float blk_sum512(float v, float* red, int tid) {
    const int lane = tid & 31, warp = tid >> 5;   // 16 warps
#pragma unroll
    for (int o = 16; o > 0; o >>= 1)
        v += __shfl_xor_sync(0xffffffffu, v, o);
    if (lane == 0) red[warp] = v;
    __syncthreads();
    if (warp == 0) {
        float t = (lane < 16) ? red[lane] : 0.f;
#pragma unroll
        for (int o = 8; o > 0; o >>= 1)
            t += __shfl_xor_sync(0xffffffffu, t, o);
        if (lane == 0) red[16] = t;
    }
    __syncthreads();
    return red[16];
}

// ---------------------------------------------------------------------------
// Fused NTM step: one block per batch b, 512 threads, 2 blocks/SM.
// ---------------------------------------------------------------------------
__global__ void __launch_bounds__(512, 2) fused_ntm(
        const float* __restrict__ mem,   const float* __restrict__ kk,
        const float* __restrict__ beta,  const float* __restrict__ gg,
        const float* __restrict__ ss,    const float* __restrict__ gamma,
        const float* __restrict__ wprev, const float* __restrict__ ee,
        const float* __restrict__ aa,    float* __restrict__ out) {
    const int b   = blockIdx.x;
    const int tid = threadIdx.x;
    const int ml  = tid & 15;           // float4 lane within a row
    const int rg  = tid >> 4;           // row group 0..31

    __shared__ float  s_sc[Ndim];       // scores
    __shared__ float  s_wg[Ndim];       // interpolated weights
    __shared__ float  s_w [Ndim];       // final weights
    __shared__ float  s_wp[Ndim];       // prefetched wprev
    __shared__ float  redA[17];
    __shared__ float  redB[17];
    __shared__ float4 s_pf[2 * 512];    // phase-3 prefetch (grp3, j=0..1)
    __shared__ float4 s_r[512];

    const float* mb = mem + (size_t)b * Ndim * Mdim;

    // prefetch wprev row into smem (group #1)
    cp_async8(&s_wp[tid * 2], wprev + b * Ndim + tid * 2);
    CP_COMMIT();

    // ---- hoist ALL per-b scalars & small vectors to kernel start ----
    const float bet = beta[b];
    const float gv  = gg[b];
    const float gm  = gamma[b];
    const float sh0 = ss[b * 3 + 0], sh1 = ss[b * 3 + 1], sh2 = ss[b * 3 + 2];
    const float4 e4 = *(const float4*)(ee + b * Mdim + ml * 4);
    const float4 a4 = *(const float4*)(aa + b * Mdim + ml * 4);

    // ---- k (+eps) and its norm (reduced within each 16-lane group) ----
    float4 k4 = *(const float4*)(kk + b * Mdim + ml * 4);
    const float kx = k4.x + EPSV, ky = k4.y + EPSV;
    const float kz = k4.z + EPSV, kw = k4.w + EPSV;
    float kn = kx * kx + ky * ky + kz * kz + kw * kw;
#pragma unroll
    for (int o = 8; o > 0; o >>= 1) kn += __shfl_xor_sync(0xffffffffu, kn, o);
    const float knorm = fmaxf(sqrtf(kn), COS_EPS);

    // ---- Phase 1: scores. 4 groups x 8 front-batched LDG.128,
    //      butterfly reduce-scatter of 16 values over the 16-lane group ----
#pragma unroll
    for (int grp = 0; grp < 4; grp++) {
        float4 m[8];
#pragma unroll
        for (int j = 0; j < 8; j++) {
            const int n = grp * 256 + j * 32 + rg;
            m[j] = *(const float4*)(mb + (size_t)n * Mdim + ml * 4);
        }
        float v[16];
#pragma unroll
        for (int j = 0; j < 8; j++) {
            const float ax = m[j].x + EPSV, ay = m[j].y + EPSV;
            const float az = m[j].z + EPSV, aw = m[j].w + EPSV;
            float d = ax * kx; d = fmaf(ay, ky, d); d = fmaf(az, kz, d); d = fmaf(aw, kw, d);
            float s = ax * ax; s = fmaf(ay, ay, s); s = fmaf(az, az, s); s = fmaf(aw, aw, s);
            v[j]     = d;      // index j      -> lane j      gets dot of row j
            v[8 + j] = s;      // index 8 + j  -> lane 8 + j  gets ssq of row j
        }
        // reduce-scatter butterfly: lane ml ends with full sum of v[ml]
        int cnt = 16;
#pragma unroll
        for (int o = 8; o >= 1; o >>= 1) {
            cnt >>= 1;
            const bool hi = (ml & o);
#pragma unroll
            for (int i = 0; i < cnt; i++) {
                const float send = hi ? v[i] : v[i + cnt];
                const float recv = __shfl_xor_sync(0xffffffffu, send, o);
                v[i] = (hi ? v[i + cnt] : v[i]) + recv;
            }
        }
        // lanes ml<8 hold dot of row j=ml; lanes ml>=8 hold ssq of row j=ml-8
        const float other = __shfl_xor_sync(0xffffffffu, v[0], 8);
        if (ml < 8) {
            const int n = grp * 256 + ml * 32 + rg;
            s_sc[n] = bet * (v[0] / (fmaxf(sqrtf(other), COS_EPS) * knorm));
        }
    }

    // prefetch phase-3's first 2 slices (grp3, j=0..1) into smem (group #2)
#pragma unroll
    for (int j = 0; j < 2; j++) {
        const int n = 3 * 256 + j * 32 + rg;
        cp_async16(&s_pf[j * 512 + tid], mb + (size_t)n * Mdim + ml * 4);
    }
    CP_COMMIT();
    __syncthreads();

    // ---- Phase 2: softmax (no max: |score| <= ~1) / interpolate / shift /
    //      sharpen. 2 n per thread. ----
    {
        const int n0 = tid, n1 = tid + 512;
        const float ex0 = __expf(s_sc[n0]);
        const float ex1 = __expf(s_sc[n1]);
        const float esum = blk_sum512(ex0 + ex1, redA, tid);
        const float inv_esum = 1.f / esum;

        CP_WAIT(1);                         // wprev prefetch complete
        const float wp0 = s_wp[n0];
        const float wp1 = s_wp[n1];
        const float wg0 = fmaf(gv, ex0 * inv_esum - wp0, wp0);
        const float wg1 = fmaf(gv, ex1 * inv_esum - wp1, wp1);
        s_wg[n0] = wg0;
        s_wg[n1] = wg1;
        __syncthreads();

        const float wh0 = sh0 * s_wg[(n0 + Ndim - 1) & (Ndim - 1)]
                        + sh1 * wg0 + sh2 * s_wg[(n0 + 1) & (Ndim - 1)];
        const float wh1 = sh0 * s_wg[(n1 + Ndim - 1) & (Ndim - 1)]
                        + sh1 * wg1 + sh2 * s_wg[(n1 + 1) & (Ndim - 1)];
        const float w0 = __powf(wh0, gm);
        const float w1 = __powf(wh1, gm);
        const float wsum = blk_sum512(w0 + w1, redB, tid);
        const float inv = 1.f / (wsum + EPSV);
        s_w[n0] = w0 * inv;
        s_w[n1] = w1 * inv;
    }
    __syncthreads();

    // ---- Phase 3: read vector + erase/add write (reverse order, batched) ----
    float* ob = out + (size_t)b * (Ndim + 1) * Mdim;

    float rx = 0.f, ry = 0.f, rz = 0.f, rw = 0.f;
    CP_WAIT(0);                             // grp3 j0/j1 prefetch complete
#pragma unroll
    for (int grp = 3; grp >= 0; grp--) {
        float4 m[8];
#pragma unroll
        for (int j = 0; j < 8; j++) {
            const int n = grp * 256 + j * 32 + rg;
            if (grp == 3 && j < 2)
                m[j] = s_pf[j * 512 + tid];
            else
                m[j] = __ldcs((const float4*)(mb + (size_t)n * Mdim + ml * 4));
        }
#pragma unroll
        for (int j = 0; j < 8; j++) {
            const int n = grp * 256 + j * 32 + rg;
            const float wv = s_w[n];
            float4 o4;
            o4.x = fmaf(m[j].x, fmaf(-wv, e4.x, 1.f), wv * a4.x);
            o4.y = fmaf(m[j].y, fmaf(-wv, e4.y, 1.f), wv * a4.y);
            o4.z = fmaf(m[j].z, fmaf(-wv, e4.z, 1.f), wv * a4.z);
            o4.w = fmaf(m[j].w, fmaf(-wv, e4.w, 1.f), wv * a4.w);
            __stcs((float4*)(ob + (size_t)(1 + n) * Mdim + ml * 4), o4);
            rx = fmaf(wv, m[j].x, rx);
            ry = fmaf(wv, m[j].y, ry);
            rz = fmaf(wv, m[j].z, rz);
            rw = fmaf(wv, m[j].w, rw);
        }
    }

    // reduce read accumulators (512 -> 16 lanes of ml)
    s_r[tid] = make_float4(rx, ry, rz, rw);
    __syncthreads();
#pragma unroll
    for (int s = 256; s >= 16; s >>= 1) {
        if (tid < s) {
            float4 x = s_r[tid], y = s_r[tid + s];
            x.x += y.x; x.y += y.y; x.z += y.z; x.w += y.w;
            s_r[tid] = x;
        }
        __syncthreads();
    }
    if (tid < 16) __stcs((float4*)(ob + tid * 4), s_r[tid]);   // read row
}

// ---------------------------------------------------------------------------
extern "C" void kernel_launch(void* const* d_in, const int* in_sizes, int n_in,
                              void* d_out, int out_size) {
    const float* mem   = (const float*)d_in[0];
    const float* kk    = (const float*)d_in[1];
    const float* beta  = (const float*)d_in[2];
    const float* gg    = (const float*)d_in[3];
    const float* ss    = (const float*)d_in[4];
    const float* gamma = (const float*)d_in[5];
    const float* wprev = (const float*)d_in[6];
    const float* ee    = (const float*)d_in[7];
    const float* aa    = (const float*)d_in[8];
    float* out = (float*)d_out;

    fused_ntm<<<Bdim, 512>>>(mem, kk, beta, gg, ss, gamma, wprev, ee, aa, out);
}